// round 7
// baseline (speedup 1.0000x reference)
#include <cuda_runtime.h>
#include <cstdint>

// Problem constants (fixed shapes per reference setup_inputs)
#define BQ   2048      // queries
#define NK   100000    // capacity
#define DIM  128       // key size
#define TOPK 50
#define DELTA 1e-3f

#define NPART 8
#define PARTK (NK / NPART)          // 12500
#define CANDM (NPART * TOPK)        // 400
#define MRG   512                   // merge sort width (>= CANDM, pow2)

// ---------------- scratch (static device globals; no runtime allocation) ----
__device__ float g_score[(size_t)BQ * NK];   // ~819 MB score matrix
__device__ float g_keynorm[NK];
__device__ float g_qnorm[BQ];
__device__ int   g_topk[BQ * TOPK];
__device__ float g_pv[BQ * NPART * TOPK];
__device__ int   g_pi[BQ * NPART * TOPK];

static __device__ __forceinline__ float finf() { return __int_as_float(0x7f800000); }

// packed dual-fp32 FMA: each 32-bit lane rounds exactly like scalar FFMA
static __device__ __forceinline__ unsigned long long ffma2(unsigned long long a,
                                                           unsigned long long b,
                                                           unsigned long long c) {
    unsigned long long d;
    asm("fma.rn.f32x2 %0, %1, %2, %3;" : "=l"(d) : "l"(a), "l"(b), "l"(c));
    return d;
}
static __device__ __forceinline__ unsigned long long splat2(float x) {
    unsigned long long d;
    unsigned int u = __float_as_uint(x);
    asm("mov.b64 %0, {%1, %2};" : "=l"(d) : "r"(u), "r"(u));
    return d;
}
static __device__ __forceinline__ float lo32(unsigned long long v) {
    return __uint_as_float((unsigned int)(v & 0xffffffffull));
}
static __device__ __forceinline__ float hi32(unsigned long long v) {
    return __uint_as_float((unsigned int)(v >> 32));
}

// ---------------- K0: row squared norms, XLA row-reduce replica -------------
// (DO NOT TOUCH — this exact rounding/grouping is what makes selection match)
__global__ void norms_kernel(const float* __restrict__ src, int rows, int which) {
    int warp = (blockIdx.x * blockDim.x + threadIdx.x) >> 5;
    int lane = threadIdx.x & 31;
    if (warp >= rows) return;
    const float* r = src + (size_t)warp * DIM;
    float acc = 0.f;
#pragma unroll
    for (int pass = 0; pass < 2; pass++) {
        int base = pass * 64 + 2 * lane;
        float v0 = r[base];
        float v1 = r[base + 1];
        acc = __fadd_rn(acc, __fmul_rn(v0, v0));
        acc = __fadd_rn(acc, __fmul_rn(v1, v1));
    }
#pragma unroll
    for (int s = 16; s; s >>= 1)
        acc = __fadd_rn(acc, __shfl_xor_sync(0xffffffffu, acc, s));
    if (lane == 0) {
        if (which == 0) g_keynorm[warp] = acc;
        else            g_qnorm[warp]   = acc;
    }
}

// ---------------- K1: FFMA2 tiled GEMM -> scores ----------------------------
// 128x128 tile, 8x8 per thread, packed f32x2 along n. Bit-identical to the
// scalar version: each output has its own accumulator, ascending-k FMA chain.
#define TM 128
#define TN 128
#define TKK 16

__global__ __launch_bounds__(256, 2) void score_gemm(const float* __restrict__ Q,
                                                     const float* __restrict__ Kd) {
    __shared__ float As[TKK][TM];
    __shared__ float Bs[TKK][TN];

    int n0 = blockIdx.x * TN;
    int b0 = blockIdx.y * TM;
    int tid = threadIdx.x;
    int tx = tid & 15;    // n: 16 groups of 8
    int ty = tid >> 4;    // m: 16 groups of 8

    unsigned long long acc[8][4];
#pragma unroll
    for (int i = 0; i < 8; i++)
#pragma unroll
        for (int j = 0; j < 4; j++) acc[i][j] = 0ull;

    int lrow = tid >> 1;          // 0..127
    int lhalf = (tid & 1) * 8;    // 0 or 8 within k-slab

    for (int k0 = 0; k0 < DIM; k0 += TKK) {
        // stage to regs
        float4 a0 = *(const float4*)(Q + (size_t)(b0 + lrow) * DIM + k0 + lhalf);
        float4 a1 = *(const float4*)(Q + (size_t)(b0 + lrow) * DIM + k0 + lhalf + 4);
        int krow = n0 + lrow;
        float4 c0 = make_float4(0.f, 0.f, 0.f, 0.f);
        float4 c1 = make_float4(0.f, 0.f, 0.f, 0.f);
        if (krow < NK) {
            c0 = *(const float4*)(Kd + (size_t)krow * DIM + k0 + lhalf);
            c1 = *(const float4*)(Kd + (size_t)krow * DIM + k0 + lhalf + 4);
        }
        __syncthreads();
        As[lhalf + 0][lrow] = a0.x; As[lhalf + 1][lrow] = a0.y;
        As[lhalf + 2][lrow] = a0.z; As[lhalf + 3][lrow] = a0.w;
        As[lhalf + 4][lrow] = a1.x; As[lhalf + 5][lrow] = a1.y;
        As[lhalf + 6][lrow] = a1.z; As[lhalf + 7][lrow] = a1.w;
        Bs[lhalf + 0][lrow] = c0.x; Bs[lhalf + 1][lrow] = c0.y;
        Bs[lhalf + 2][lrow] = c0.z; Bs[lhalf + 3][lrow] = c0.w;
        Bs[lhalf + 4][lrow] = c1.x; Bs[lhalf + 5][lrow] = c1.y;
        Bs[lhalf + 6][lrow] = c1.z; Bs[lhalf + 7][lrow] = c1.w;
        __syncthreads();

#pragma unroll
        for (int kk = 0; kk < TKK; kk++) {
            // b pairs straight from shared as 64-bit lanes (no pack movs)
            const ulonglong2* bp = reinterpret_cast<const ulonglong2*>(&Bs[kk][tx * 8]);
            ulonglong2 b01 = bp[0];   // n cols 0,1 | 2,3
            ulonglong2 b23 = bp[1];   // n cols 4,5 | 6,7
            const float4* ap = reinterpret_cast<const float4*>(&As[kk][ty * 8]);
            float4 af0 = ap[0], af1 = ap[1];
            float av[8] = {af0.x, af0.y, af0.z, af0.w, af1.x, af1.y, af1.z, af1.w};
#pragma unroll
            for (int i = 0; i < 8; i++) {
                unsigned long long s = splat2(av[i]);
                acc[i][0] = ffma2(s, b01.x, acc[i][0]);
                acc[i][1] = ffma2(s, b01.y, acc[i][1]);
                acc[i][2] = ffma2(s, b23.x, acc[i][2]);
                acc[i][3] = ffma2(s, b23.y, acc[i][3]);
            }
        }
    }

    // epilogue: (qn - 2*dot) + kn, same rounding sequence as the passing kernel
    int nbase = n0 + tx * 8;
    bool ok0 = (nbase + 3) < NK;
    bool ok1 = (nbase + 7) < NK;
    float kn[8];
#pragma unroll
    for (int j = 0; j < 8; j++) kn[j] = (nbase + j < NK) ? g_keynorm[nbase + j] : 0.f;

#pragma unroll
    for (int i = 0; i < 8; i++) {
        int bb = b0 + ty * 8 + i;
        float qn = g_qnorm[bb];
        float c[8];
#pragma unroll
        for (int j = 0; j < 4; j++) { c[2 * j] = lo32(acc[i][j]); c[2 * j + 1] = hi32(acc[i][j]); }
        float r[8];
#pragma unroll
        for (int j = 0; j < 8; j++)
            r[j] = __fadd_rn(__fsub_rn(qn, 2.f * c[j]), kn[j]);
        float* dst = &g_score[(size_t)bb * NK + nbase];
        if (ok0) *(float4*)dst       = make_float4(r[0], r[1], r[2], r[3]);
        if (ok1) *(float4*)(dst + 4) = make_float4(r[4], r[5], r[6], r[7]);
    }
}

// ---------------- shared bitonic sort by (value, index) ascending -----------
template <int N>
static __device__ void sort_sh(float* sv, int* si, int tid) {
    for (int k = 2; k <= N; k <<= 1) {
        for (int j = k >> 1; j > 0; j >>= 1) {
            for (int i = tid; i < N; i += 256) {
                int ixj = i ^ j;
                if (ixj > i) {
                    float v1 = sv[i], v2 = sv[ixj];
                    int  i1 = si[i],  i2 = si[ixj];
                    bool up   = ((i & k) == 0);
                    bool less = (v1 < v2) || (v1 == v2 && i1 < i2);
                    if (less != up) {
                        sv[i] = v2; sv[ixj] = v1;
                        si[i] = i2; si[ixj] = i1;
                    }
                }
            }
            __syncthreads();
        }
    }
}

// ---------------- K2a: per-partition top-50 (deterministic scan-push) -------
#define POOL  2048
#define CHUNK 1024

__global__ __launch_bounds__(256) void topk_part() {
    int b    = blockIdx.x;
    int part = blockIdx.y;
    int tid  = threadIdx.x;
    int lane = tid & 31;
    int wid  = tid >> 5;
    const float* row = g_score + (size_t)b * NK + (size_t)part * PARTK;
    int gbase = part * PARTK;

    __shared__ float sv[POOL];
    __shared__ int   si[POOL];
    __shared__ int   s_cnt;
    __shared__ float s_tau;
    __shared__ int   s_wsum[8];
    __shared__ int   s_woff[8];
    __shared__ int   s_total;

    if (tid == 0) { s_cnt = 0; s_tau = finf(); }
    __syncthreads();

    const int nChunks = (PARTK + CHUNK - 1) / CHUNK;   // 13
    for (int c = 0; c < nChunks; c++) {
        int   base = c * CHUNK;
        float tau  = s_tau;

        float vals[4]; int idxs[4];
        int mycnt = 0;
        int i4 = base + tid * 4;
        if (i4 < PARTK) {   // PARTK % 4 == 0 => full float4 or nothing
            float4 v = *(const float4*)(row + i4);
            float vv[4] = {v.x, v.y, v.z, v.w};
#pragma unroll
            for (int e = 0; e < 4; e++) {
                if (vv[e] <= tau) { vals[mycnt] = vv[e]; idxs[mycnt] = gbase + i4 + e; mycnt++; }
            }
        }

        // deterministic block scan placement
        int scan = mycnt;
#pragma unroll
        for (int s = 1; s < 32; s <<= 1) {
            int t = __shfl_up_sync(0xffffffffu, scan, s);
            if (lane >= s) scan += t;
        }
        if (lane == 31) s_wsum[wid] = scan;
        __syncthreads();
        if (tid == 0) {
            int run = 0;
#pragma unroll
            for (int w = 0; w < 8; w++) { s_woff[w] = run; run += s_wsum[w]; }
            s_total = run;
        }
        __syncthreads();

        int pos = s_cnt + s_woff[wid] + (scan - mycnt);
        for (int k = 0; k < mycnt; k++) { sv[pos + k] = vals[k]; si[pos + k] = idxs[k]; }
        __syncthreads();
        if (tid == 0) s_cnt += s_total;
        __syncthreads();

        if (s_cnt > POOL - CHUNK) {
            int cnt = s_cnt;
            for (int i = tid; i < POOL; i += 256)
                if (i >= cnt) { sv[i] = finf(); si[i] = 0x7fffffff; }
            __syncthreads();
            sort_sh<POOL>(sv, si, tid);
            if (tid == 0) { s_cnt = TOPK; s_tau = sv[TOPK - 1]; }
            __syncthreads();
        }
    }

    {
        int cnt = s_cnt;
        for (int i = tid; i < POOL; i += 256)
            if (i >= cnt) { sv[i] = finf(); si[i] = 0x7fffffff; }
        __syncthreads();
        sort_sh<POOL>(sv, si, tid);
    }
    if (tid < TOPK) {
        int o = (b * NPART + part) * TOPK + tid;
        g_pv[o] = sv[tid];
        g_pi[o] = si[tid];
    }
}

// ---------------- K2b: merge 8x50 partition candidates -> global top-50 -----
__global__ __launch_bounds__(256) void topk_merge() {
    int b   = blockIdx.x;
    int tid = threadIdx.x;
    __shared__ float sv[MRG];
    __shared__ int   si[MRG];

    for (int i = tid; i < MRG; i += 256) {
        if (i < CANDM) { sv[i] = g_pv[b * CANDM + i]; si[i] = g_pi[b * CANDM + i]; }
        else           { sv[i] = finf();              si[i] = 0x7fffffff; }
    }
    __syncthreads();
    sort_sh<MRG>(sv, si, tid);

    if (tid < TOPK) {
        int ki = si[tid];
        if (ki < 0) ki = 0;
        if (ki >= NK) ki = NK - 1;   // fail-soft: never emit OOB index
        g_topk[b * TOPK + tid] = ki;
    }
}

// ---------------- K3: fp32 recompute (as reference) + weighting -------------
__global__ __launch_bounds__(128) void out_kernel(const float* __restrict__ Q,
                                                  const float* __restrict__ Kd,
                                                  const float* __restrict__ V,
                                                  float* __restrict__ out) {
    int b    = blockIdx.x;
    int lane = threadIdx.x & 31;
    int warp = threadIdx.x >> 5;
    __shared__ float sqd[TOPK];

    const float* qr = Q + (size_t)b * DIM;
    for (int j = warp; j < TOPK; j += 4) {
        int ki = g_topk[b * TOPK + j];
        const float* kr = Kd + (size_t)ki * DIM;
        float acc = 0.f;
#pragma unroll
        for (int m = 0; m < 4; m++) {
            float d = qr[lane + 32 * m] - kr[lane + 32 * m];
            float p = __fmul_rn(d, d);
            acc = __fadd_rn(acc, p);
        }
#pragma unroll
        for (int s = 16; s; s >>= 1) acc += __shfl_xor_sync(0xffffffffu, acc, s);
        if (lane == 0) sqd[j] = acc;
    }
    __syncthreads();

    if (threadIdx.x == 0) {
        float s1 = 0.f, s2 = 0.f;
        for (int j = 0; j < TOPK; j++) {
            float w = 1.f / (sqd[j] + DELTA);
            s1 += w;
            s2 += w * V[g_topk[b * TOPK + j]];
        }
        out[b] = s2 / s1;
    }
}

// ---------------- launch ----------------------------------------------------
extern "C" void kernel_launch(void* const* d_in, const int* in_sizes, int n_in,
                              void* d_out, int out_size) {
    const float* Q  = nullptr;   // 262144 elems
    const float* Kd = nullptr;   // 12800000 elems
    const float* V  = nullptr;   // 100000 elems
    for (int i = 0; i < n_in; i++) {
        if      (in_sizes[i] == BQ * DIM) Q  = (const float*)d_in[i];
        else if (in_sizes[i] == NK * DIM) Kd = (const float*)d_in[i];
        else if (in_sizes[i] == NK)       V  = (const float*)d_in[i];
    }
    float* out = (float*)d_out;
    if (!Q || !Kd || !V) return;

    norms_kernel<<<(NK + 7) / 8, 256>>>(Kd, NK, 0);
    norms_kernel<<<(BQ + 7) / 8, 256>>>(Q,  BQ, 1);

    dim3 grid((NK + TN - 1) / TN, BQ / TM);   // 782 x 16
    score_gemm<<<grid, 256>>>(Q, Kd);

    dim3 tgrid(BQ, NPART);
    topk_part<<<tgrid, 256>>>();
    topk_merge<<<BQ, 256>>>();

    out_kernel<<<BQ, 128>>>(Q, Kd, V, out);
}